// round 1
// baseline (speedup 1.0000x reference)
#include <cuda_runtime.h>
#include <cstdint>

#define NN 50000
#define NE 800000

// Scratch (static device arrays: allocation-free per harness rules)
__device__ float g_tmp[NN * 128];
__device__ float g_acc[NN * 128];
__device__ float g_h[NN * 128];
__device__ float g_dinv[NN];
__device__ int   g_deg[NN];

// ---------------------------------------------------------------------------
// degree / normalization
// ---------------------------------------------------------------------------
__global__ void k_deg_init(int* __restrict__ deg) {
    int i = blockIdx.x * blockDim.x + threadIdx.x;
    if (i < NN) deg[i] = 1;  // self-loop
}

__global__ void k_deg_count(const int* __restrict__ ei, int* __restrict__ deg) {
    int e = blockIdx.x * blockDim.x + threadIdx.x;
    if (e < NE) atomicAdd(&deg[ei[NE + e]], 1);  // dst row of edge_index
}

__global__ void k_dinv(const int* __restrict__ deg, float* __restrict__ dinv) {
    int i = blockIdx.x * blockDim.x + threadIdx.x;
    if (i < NN) dinv[i] = rsqrtf((float)deg[i]);
}

// ---------------------------------------------------------------------------
// GEMM: out[n][c] = sum_k A[n][k] * W[k][c], optional row scale (dinv),
// optional bias, optional duplicate store (acc init for self-loop).
// BM=64 rows per block, BN cols. Inner loop uses packed fma.rn.f32x2 (FFMA2)
// for 2x fp32 FMA throughput on sm_103a.
// ---------------------------------------------------------------------------
union U64F2 { unsigned long long u; float2 f; };

#define FFMA2(d, a, b) asm("fma.rn.f32x2 %0, %1, %2, %0;" : "+l"(d) : "l"(a), "l"(b))

template <int BN>
__global__ void k_gemm(const float* __restrict__ A, const float* __restrict__ W,
                       const float* __restrict__ scale, const float* __restrict__ bias,
                       float* __restrict__ out0, float* __restrict__ out1, int nrows) {
    constexpr int BM = 64;
    constexpr int TX = BN / 4;   // thread cols
    constexpr int TY = BM / 4;   // thread rows
    constexpr int NT = TX * TY;

    extern __shared__ float smem[];
    float*  Ws = smem;                          // [128][BN]
    float2* Ad = (float2*)(smem + 128 * BN);    // [128][BM] duplicated-pair A^T
    float*  As = (float*)(Ad + 128 * BM);       // [BM][129] staging (padded)

    const int tid  = threadIdx.x;
    const int row0 = blockIdx.x * BM;

    // Load weights (coalesced)
    for (int idx = tid; idx < 128 * BN; idx += NT) Ws[idx] = W[idx];
    // Load A tile coalesced into padded staging buffer
    for (int idx = tid; idx < BM * 128; idx += NT) {
        int r = idx >> 7, k = idx & 127;
        int gr = row0 + r;
        As[r * 129 + k] = (gr < nrows) ? A[(size_t)gr * 128 + k] : 0.0f;
    }
    __syncthreads();
    // Transpose + duplicate into Ad[k][r] = (a,a)  (conflict-free both sides)
    for (int idx = tid; idx < 128 * BM; idx += NT) {
        int r = idx % BM, k = idx / BM;
        float v = As[r * 129 + k];
        Ad[idx] = make_float2(v, v);
    }
    __syncthreads();

    const int tc = tid % TX, tr = tid / TX;
    unsigned long long acc[4][2];
#pragma unroll
    for (int r = 0; r < 4; r++) { acc[r][0] = 0ull; acc[r][1] = 0ull; }

    const float2* adp = Ad + 4 * tr;
    const float*  wsp = Ws + 4 * tc;

#pragma unroll 8
    for (int k = 0; k < 128; k++) {
        ulonglong2 av0 = *(const ulonglong2*)(adp + (size_t)k * BM);
        ulonglong2 av1 = *(const ulonglong2*)(adp + (size_t)k * BM + 2);
        ulonglong2 wv  = *(const ulonglong2*)(wsp + (size_t)k * BN);
        FFMA2(acc[0][0], av0.x, wv.x); FFMA2(acc[0][1], av0.x, wv.y);
        FFMA2(acc[1][0], av0.y, wv.x); FFMA2(acc[1][1], av0.y, wv.y);
        FFMA2(acc[2][0], av1.x, wv.x); FFMA2(acc[2][1], av1.x, wv.y);
        FFMA2(acc[3][0], av1.y, wv.x); FFMA2(acc[3][1], av1.y, wv.y);
    }

#pragma unroll
    for (int r = 0; r < 4; r++) {
        int row = row0 + 4 * tr + r;
        if (row >= nrows) break;
        U64F2 u0, u1;
        u0.u = acc[r][0];
        u1.u = acc[r][1];
        float4 v = make_float4(u0.f.x, u0.f.y, u1.f.x, u1.f.y);
        if (scale) {
            float s = scale[row];
            v.x *= s; v.y *= s; v.z *= s; v.w *= s;
        }
        if (bias) {
            v.x += bias[4 * tc + 0]; v.y += bias[4 * tc + 1];
            v.z += bias[4 * tc + 2]; v.w += bias[4 * tc + 3];
        }
        *(float4*)(out0 + (size_t)row * BN + 4 * tc) = v;
        if (out1) *(float4*)(out1 + (size_t)row * BN + 4 * tc) = v;
    }
}

// ---------------------------------------------------------------------------
// Edge scatter: acc[dst] += tmp[src]  (unscaled; norm factored out).
// One warp per edge, 128 floats = 32 lanes x float4, vectorized RED.128.
// ---------------------------------------------------------------------------
__global__ void k_scatter(const int* __restrict__ ei, const float* __restrict__ tmp,
                          float* __restrict__ acc) {
    int gwarp = (blockIdx.x * blockDim.x + threadIdx.x) >> 5;
    int lane  = threadIdx.x & 31;
    if (gwarp >= NE) return;
    int src = __ldg(&ei[gwarp]);
    int dst = __ldg(&ei[NE + gwarp]);
    float4 v = ((const float4*)(tmp + (size_t)src * 128))[lane];
    float* d = acc + (size_t)dst * 128 + lane * 4;
    asm volatile("red.global.add.v4.f32 [%0], {%1, %2, %3, %4};"
                 :: "l"(d), "f"(v.x), "f"(v.y), "f"(v.z), "f"(v.w)
                 : "memory");
}

// ---------------------------------------------------------------------------
// Finalize: h = relu(dinv[node] * acc + bias)
// ---------------------------------------------------------------------------
__global__ void k_finalize(const float* __restrict__ acc, const float* __restrict__ dinv,
                           const float* __restrict__ bias, float* __restrict__ out) {
    int i = blockIdx.x * blockDim.x + threadIdx.x;  // over NN*32 float4s
    if (i >= NN * 32) return;
    int node = i >> 5;
    int c4 = i & 31;
    float s = dinv[node];
    float4 v = ((const float4*)acc)[i];
    float4 b = ((const float4*)bias)[c4];
    v.x = fmaxf(fmaf(v.x, s, b.x), 0.0f);
    v.y = fmaxf(fmaf(v.y, s, b.y), 0.0f);
    v.z = fmaxf(fmaf(v.z, s, b.z), 0.0f);
    v.w = fmaxf(fmaf(v.w, s, b.w), 0.0f);
    ((float4*)out)[i] = v;
}

// ---------------------------------------------------------------------------
extern "C" void kernel_launch(void* const* d_in, const int* in_sizes, int n_in,
                              void* d_out, int out_size) {
    const float* x  = (const float*)d_in[0];
    const int*   ei = (const int*)d_in[1];
    const float* W1 = (const float*)d_in[2];
    const float* b1 = (const float*)d_in[3];
    const float* W2 = (const float*)d_in[4];
    const float* b2 = (const float*)d_in[5];
    const float* W3 = (const float*)d_in[6];
    const float* b3 = (const float*)d_in[7];
    const float* Wc = (const float*)d_in[8];
    const float* bc = (const float*)d_in[9];

    float* out_logits = (float*)d_out;                  // [NN,40]
    float* out_h      = (float*)d_out + (size_t)NN * 40;  // [NN,128]

    float *tmp, *acc, *h, *dinv;
    int* deg;
    cudaGetSymbolAddress((void**)&tmp,  g_tmp);
    cudaGetSymbolAddress((void**)&acc,  g_acc);
    cudaGetSymbolAddress((void**)&h,    g_h);
    cudaGetSymbolAddress((void**)&dinv, g_dinv);
    cudaGetSymbolAddress((void**)&deg,  g_deg);

    const int SM128 = 128 * 128 * 4 + 128 * 64 * 8 + 64 * 129 * 4;
    const int SM40  = 128 * 40 * 4  + 128 * 64 * 8 + 64 * 129 * 4;
    cudaFuncSetAttribute(k_gemm<128>, cudaFuncAttributeMaxDynamicSharedMemorySize, SM128);
    cudaFuncSetAttribute(k_gemm<40>,  cudaFuncAttributeMaxDynamicSharedMemorySize, SM40);

    // normalization
    k_deg_init<<<(NN + 255) / 256, 256>>>(deg);
    k_deg_count<<<(NE + 255) / 256, 256>>>(ei, deg);
    k_dinv<<<(NN + 255) / 256, 256>>>(deg, dinv);

    const int gblk = (NN + 63) / 64;
    const int sblk = NE / 8;                 // 1 warp per edge, 8 warps/block
    const int fblk = (NN * 32 + 255) / 256;

    // layer 1: tmp = (x@W1)*dinv ; acc = tmp (self-loop) ; scatter ; relu
    k_gemm<128><<<gblk, 512, SM128>>>(x, W1, dinv, nullptr, tmp, acc, NN);
    k_scatter<<<sblk, 256>>>(ei, tmp, acc);
    k_finalize<<<fblk, 256>>>(acc, dinv, b1, h);

    // layer 2
    k_gemm<128><<<gblk, 512, SM128>>>(h, W2, dinv, nullptr, tmp, acc, NN);
    k_scatter<<<sblk, 256>>>(ei, tmp, acc);
    k_finalize<<<fblk, 256>>>(acc, dinv, b2, h);

    // layer 3 -> h output region
    k_gemm<128><<<gblk, 512, SM128>>>(h, W3, dinv, nullptr, tmp, acc, NN);
    k_scatter<<<sblk, 256>>>(ei, tmp, acc);
    k_finalize<<<fblk, 256>>>(acc, dinv, b3, out_h);

    // classifier: logits = h3 @ Wc + bc
    k_gemm<40><<<gblk, 160, SM40>>>(out_h, Wc, nullptr, bc, out_logits, nullptr, NN);
}

// round 3
// speedup vs baseline: 1.9693x; 1.9693x over previous
#include <cuda_runtime.h>
#include <cstdint>

#define NN 50000
#define NE 800000
#define NB 98   // scan blocks: 98*512 >= 50000

// ---------------------------------------------------------------------------
// Scratch (static device arrays: allocation-free per harness rules)
// ---------------------------------------------------------------------------
__device__ float g_tmp[NN * 128];
__device__ float g_h[NN * 128];
__device__ float g_dinv[NN];
__device__ int   g_deg[NN];
__device__ int   g_rowptr[NN + 1];
__device__ int   g_cursor[NN];
__device__ int   g_csr[NE];
__device__ int   g_bsum[NB];

// ---------------------------------------------------------------------------
// degree / normalization
// ---------------------------------------------------------------------------
__global__ void k_deg_init(int* __restrict__ deg) {
    int i = blockIdx.x * blockDim.x + threadIdx.x;
    if (i < NN) deg[i] = 1;  // self-loop
}
__global__ void k_deg_count(const int* __restrict__ ei, int* __restrict__ deg) {
    int e = blockIdx.x * blockDim.x + threadIdx.x;
    if (e < NE) atomicAdd(&deg[ei[NE + e]], 1);
}
__global__ void k_dinv(const int* __restrict__ deg, float* __restrict__ dinv) {
    int i = blockIdx.x * blockDim.x + threadIdx.x;
    if (i < NN) dinv[i] = rsqrtf((float)deg[i]);
}

// ---------------------------------------------------------------------------
// CSR build: exclusive scan of edge counts (deg-1), then cursor fill.
// ---------------------------------------------------------------------------
__global__ void k_scan1(const int* __restrict__ deg, int* __restrict__ rowptr,
                        int* __restrict__ bsum) {
    __shared__ int s[512];
    int tid = threadIdx.x;
    int i = blockIdx.x * 512 + tid;
    int v = (i < NN) ? (deg[i] - 1) : 0;   // edges only (self handled separately)
    s[tid] = v;
    __syncthreads();
    for (int o = 1; o < 512; o <<= 1) {
        int t = (tid >= o) ? s[tid - o] : 0;
        __syncthreads();
        s[tid] += t;
        __syncthreads();
    }
    if (i < NN) rowptr[i] = s[tid] - v;    // exclusive within block
    if (tid == 511) bsum[blockIdx.x] = s[511];
}
__global__ void k_scan2(int* __restrict__ bsum) {
    if (threadIdx.x == 0 && blockIdx.x == 0) {
        int acc = 0;
        for (int i = 0; i < NB; i++) { int v = bsum[i]; bsum[i] = acc; acc += v; }
    }
}
__global__ void k_scan3(int* __restrict__ rowptr, const int* __restrict__ bsum,
                        int* __restrict__ cursor) {
    int i = blockIdx.x * 512 + threadIdx.x;
    if (i < NN) {
        int r = rowptr[i] + bsum[blockIdx.x];
        rowptr[i] = r;
        cursor[i] = r;
    }
    if (blockIdx.x == 0 && threadIdx.x == 0) rowptr[NN] = NE;
}
__global__ void k_fill(const int* __restrict__ ei, int* __restrict__ cursor,
                       int* __restrict__ csr) {
    int e = blockIdx.x * blockDim.x + threadIdx.x;
    if (e >= NE) return;
    int dst = ei[NE + e];
    int pos = atomicAdd(&cursor[dst], 1);
    csr[pos] = ei[e];
}

// ---------------------------------------------------------------------------
// GEMM 128x128: tmp[row] = (A[row] @ W) * dinv[row]
// 512 threads, thread tile 8 rows x 4 cols, FFMA2 (fma.rn.f32x2) inner loop.
// A transposed into smem At[k][row]; W kept [k][n].
// ---------------------------------------------------------------------------
#define FFMA2(d, a, b) asm("fma.rn.f32x2 %0, %1, %2, %0;" : "+l"(d) : "l"(a), "l"(b))
#define PACK2(d, a)    asm("mov.b64 %0, {%1, %1};" : "=l"(d) : "f"(a))
union U64F2 { unsigned long long u; float2 f; };

// smem: Ws[128*128] + At[128*128] + staging[128*129]
static constexpr int GM_WS  = 0;
static constexpr int GM_AT  = 128 * 128;
static constexpr int GM_STG = 2 * 128 * 128;
static constexpr int GM_SMEM_FLOATS = 2 * 128 * 128 + 128 * 129;
static constexpr int GM_SMEM_BYTES  = GM_SMEM_FLOATS * 4;   // 197120

__global__ void __launch_bounds__(512, 1)
k_gemm128(const float* __restrict__ A, const float* __restrict__ W,
          const float* __restrict__ scale, float* __restrict__ out, int nrows) {
    extern __shared__ float sm[];
    float* Ws  = sm + GM_WS;
    float* At  = sm + GM_AT;
    float* Stg = sm + GM_STG;

    const int tid  = threadIdx.x;
    const int row0 = blockIdx.x * 128;

    // load W [k][n] directly (coalesced float4)
    {
        const float4* w4 = (const float4*)W;
        float4* s4 = (float4*)Ws;
        for (int i = tid; i < 4096; i += 512) s4[i] = w4[i];
    }
    // stage A [row][k] into padded staging (row stride 129)
    for (int i = tid; i < 4096; i += 512) {
        int r = i >> 5, kq = i & 31;
        int grow = row0 + r;
        float4 f = make_float4(0.f, 0.f, 0.f, 0.f);
        if (grow < nrows) f = ((const float4*)A)[(size_t)grow * 32 + kq];
        float* p = Stg + r * 129 + kq * 4;
        p[0] = f.x; p[1] = f.y; p[2] = f.z; p[3] = f.w;
    }
    __syncthreads();
    // transpose: At[k][r] = Stg[r][k]   (reads stride-129: conflict-free; writes contiguous)
    for (int i = tid; i < 16384; i += 512) {
        int r = i & 127, k = i >> 7;
        At[k * 128 + r] = Stg[r * 129 + k];
    }
    __syncthreads();

    const int tc = tid & 31;      // col group: cols 4*tc
    const int tr = tid >> 5;      // row group: rows 8*tr  (== warp id)

    unsigned long long acc[8][2];
#pragma unroll
    for (int i = 0; i < 8; i++) { acc[i][0] = 0ull; acc[i][1] = 0ull; }

    const float* Wp = Ws + 4 * tc;
    const float* Ap = At + 8 * tr;

#pragma unroll 4
    for (int k = 0; k < 128; k++) {
        ulonglong2 wv = *(const ulonglong2*)(Wp + k * 128);
        float4 a0 = *(const float4*)(Ap + k * 128);
        float4 a1 = *(const float4*)(Ap + k * 128 + 4);
        unsigned long long p0, p1, p2, p3, p4, p5, p6, p7;
        PACK2(p0, a0.x); PACK2(p1, a0.y); PACK2(p2, a0.z); PACK2(p3, a0.w);
        PACK2(p4, a1.x); PACK2(p5, a1.y); PACK2(p6, a1.z); PACK2(p7, a1.w);
        FFMA2(acc[0][0], p0, wv.x); FFMA2(acc[0][1], p0, wv.y);
        FFMA2(acc[1][0], p1, wv.x); FFMA2(acc[1][1], p1, wv.y);
        FFMA2(acc[2][0], p2, wv.x); FFMA2(acc[2][1], p2, wv.y);
        FFMA2(acc[3][0], p3, wv.x); FFMA2(acc[3][1], p3, wv.y);
        FFMA2(acc[4][0], p4, wv.x); FFMA2(acc[4][1], p4, wv.y);
        FFMA2(acc[5][0], p5, wv.x); FFMA2(acc[5][1], p5, wv.y);
        FFMA2(acc[6][0], p6, wv.x); FFMA2(acc[6][1], p6, wv.y);
        FFMA2(acc[7][0], p7, wv.x); FFMA2(acc[7][1], p7, wv.y);
    }

#pragma unroll
    for (int i = 0; i < 8; i++) {
        int row = row0 + 8 * tr + i;
        if (row < nrows) {
            float s = scale ? scale[row] : 1.0f;
            U64F2 u0, u1;
            u0.u = acc[i][0];
            u1.u = acc[i][1];
            float4 v = make_float4(u0.f.x * s, u0.f.y * s, u1.f.x * s, u1.f.y * s);
            *(float4*)(out + (size_t)row * 128 + 4 * tc) = v;
        }
    }
}

// ---------------------------------------------------------------------------
// Aggregate (CSR gather, atomic-free) fused with self-loop + dinv + bias + relu:
//   out[n] = relu( dinv[n] * (tmp[n] + sum_{e in row n} tmp[csr[e]]) + bias )
// One warp per node; lane owns a float4 (16B) slice.
// ---------------------------------------------------------------------------
__global__ void k_agg(const int* __restrict__ rowptr, const int* __restrict__ csr,
                      const float* __restrict__ tmp, const float* __restrict__ dinv,
                      const float* __restrict__ bias, float* __restrict__ out) {
    int w = (blockIdx.x * blockDim.x + threadIdx.x) >> 5;
    if (w >= NN) return;
    int lane = threadIdx.x & 31;
    const float4* t4 = (const float4*)tmp;

    float4 a = t4[(size_t)w * 32 + lane];   // self-loop term
    float4 a2 = make_float4(0.f, 0.f, 0.f, 0.f);

    int e   = __ldg(rowptr + w);
    int end = __ldg(rowptr + w + 1);
    for (; e + 1 < end; e += 2) {
        int s0 = __ldg(csr + e);
        int s1 = __ldg(csr + e + 1);
        float4 v0 = t4[(size_t)s0 * 32 + lane];
        float4 v1 = t4[(size_t)s1 * 32 + lane];
        a.x += v0.x;  a.y += v0.y;  a.z += v0.z;  a.w += v0.w;
        a2.x += v1.x; a2.y += v1.y; a2.z += v1.z; a2.w += v1.w;
    }
    if (e < end) {
        int s0 = __ldg(csr + e);
        float4 v0 = t4[(size_t)s0 * 32 + lane];
        a.x += v0.x; a.y += v0.y; a.z += v0.z; a.w += v0.w;
    }
    a.x += a2.x; a.y += a2.y; a.z += a2.z; a.w += a2.w;

    float sc = dinv[w];
    float4 b = ((const float4*)bias)[lane];
    a.x = fmaxf(fmaf(a.x, sc, b.x), 0.0f);
    a.y = fmaxf(fmaf(a.y, sc, b.y), 0.0f);
    a.z = fmaxf(fmaf(a.z, sc, b.z), 0.0f);
    a.w = fmaxf(fmaf(a.w, sc, b.w), 0.0f);
    ((float4*)out)[(size_t)w * 32 + lane] = a;
}

// ---------------------------------------------------------------------------
// Classifier SIMT GEMM (BN=40), FFMA2 path (proven in R1).
// ---------------------------------------------------------------------------
template <int BN>
__global__ void k_gemm_cls(const float* __restrict__ A, const float* __restrict__ W,
                           const float* __restrict__ bias,
                           float* __restrict__ out0, int nrows) {
    constexpr int BM = 64;
    constexpr int TX = BN / 4;
    constexpr int TY = BM / 4;
    constexpr int NT = TX * TY;

    extern __shared__ float fsm[];
    float*  Ws = fsm;
    float2* Ad = (float2*)(fsm + 128 * BN);
    float*  As = (float*)(Ad + 128 * BM);

    const int tid  = threadIdx.x;
    const int row0 = blockIdx.x * BM;

    for (int idx = tid; idx < 128 * BN; idx += NT) Ws[idx] = W[idx];
    for (int idx = tid; idx < BM * 128; idx += NT) {
        int r = idx >> 7, k = idx & 127;
        int gr = row0 + r;
        As[r * 129 + k] = (gr < nrows) ? A[(size_t)gr * 128 + k] : 0.0f;
    }
    __syncthreads();
    for (int idx = tid; idx < 128 * BM; idx += NT) {
        int r = idx % BM, k = idx / BM;
        float v = As[r * 129 + k];
        Ad[idx] = make_float2(v, v);
    }
    __syncthreads();

    const int tc = tid % TX, tr = tid / TX;
    unsigned long long acc[4][2];
#pragma unroll
    for (int r = 0; r < 4; r++) { acc[r][0] = 0ull; acc[r][1] = 0ull; }

    const float2* adp = Ad + 4 * tr;
    const float*  wsp = Ws + 4 * tc;

#pragma unroll 8
    for (int k = 0; k < 128; k++) {
        ulonglong2 av0 = *(const ulonglong2*)(adp + (size_t)k * BM);
        ulonglong2 av1 = *(const ulonglong2*)(adp + (size_t)k * BM + 2);
        ulonglong2 wv  = *(const ulonglong2*)(wsp + (size_t)k * BN);
        FFMA2(acc[0][0], av0.x, wv.x); FFMA2(acc[0][1], av0.x, wv.y);
        FFMA2(acc[1][0], av0.y, wv.x); FFMA2(acc[1][1], av0.y, wv.y);
        FFMA2(acc[2][0], av1.x, wv.x); FFMA2(acc[2][1], av1.x, wv.y);
        FFMA2(acc[3][0], av1.y, wv.x); FFMA2(acc[3][1], av1.y, wv.y);
    }

#pragma unroll
    for (int r = 0; r < 4; r++) {
        int row = row0 + 4 * tr + r;
        if (row >= nrows) break;
        U64F2 u0, u1;
        u0.u = acc[r][0];
        u1.u = acc[r][1];
        float4 v = make_float4(u0.f.x + bias[4 * tc + 0], u0.f.y + bias[4 * tc + 1],
                               u1.f.x + bias[4 * tc + 2], u1.f.y + bias[4 * tc + 3]);
        *(float4*)(out0 + (size_t)row * BN + 4 * tc) = v;
    }
}

// ---------------------------------------------------------------------------
extern "C" void kernel_launch(void* const* d_in, const int* in_sizes, int n_in,
                              void* d_out, int out_size) {
    const float* x  = (const float*)d_in[0];
    const int*   ei = (const int*)d_in[1];
    const float* W1 = (const float*)d_in[2];
    const float* b1 = (const float*)d_in[3];
    const float* W2 = (const float*)d_in[4];
    const float* b2 = (const float*)d_in[5];
    const float* W3 = (const float*)d_in[6];
    const float* b3 = (const float*)d_in[7];
    const float* Wc = (const float*)d_in[8];
    const float* bc = (const float*)d_in[9];

    float* out_logits = (float*)d_out;                    // [NN,40]
    float* out_h      = (float*)d_out + (size_t)NN * 40;  // [NN,128]

    float *tmp, *h, *dinv;
    int *deg, *rowptr, *cursor, *csr, *bsum;
    cudaGetSymbolAddress((void**)&tmp,    g_tmp);
    cudaGetSymbolAddress((void**)&h,      g_h);
    cudaGetSymbolAddress((void**)&dinv,   g_dinv);
    cudaGetSymbolAddress((void**)&deg,    g_deg);
    cudaGetSymbolAddress((void**)&rowptr, g_rowptr);
    cudaGetSymbolAddress((void**)&cursor, g_cursor);
    cudaGetSymbolAddress((void**)&csr,    g_csr);
    cudaGetSymbolAddress((void**)&bsum,   g_bsum);

    const int SM40 = 128 * 40 * 4 + 128 * 64 * 8 + 64 * 129 * 4;
    cudaFuncSetAttribute(k_gemm128, cudaFuncAttributeMaxDynamicSharedMemorySize, GM_SMEM_BYTES);
    cudaFuncSetAttribute(k_gemm_cls<40>, cudaFuncAttributeMaxDynamicSharedMemorySize, SM40);

    // ---- normalization + CSR build (once) ----
    k_deg_init<<<(NN + 255) / 256, 256>>>(deg);
    k_deg_count<<<(NE + 255) / 256, 256>>>(ei, deg);
    k_dinv<<<(NN + 255) / 256, 256>>>(deg, dinv);
    k_scan1<<<NB, 512>>>(deg, rowptr, bsum);
    k_scan2<<<1, 32>>>(bsum);
    k_scan3<<<NB, 512>>>(rowptr, bsum, cursor);
    k_fill<<<(NE + 255) / 256, 256>>>(ei, cursor, csr);

    const int gblk = (NN + 127) / 128;   // 391
    const int ablk = NN * 32 / 256;      // 6250
    const int cblk = (NN + 63) / 64;     // 782

    // layer 1
    k_gemm128<<<gblk, 512, GM_SMEM_BYTES>>>(x, W1, dinv, tmp, NN);
    k_agg<<<ablk, 256>>>(rowptr, csr, tmp, dinv, b1, h);
    // layer 2
    k_gemm128<<<gblk, 512, GM_SMEM_BYTES>>>(h, W2, dinv, tmp, NN);
    k_agg<<<ablk, 256>>>(rowptr, csr, tmp, dinv, b2, h);
    // layer 3 -> h output region
    k_gemm128<<<gblk, 512, GM_SMEM_BYTES>>>(h, W3, dinv, tmp, NN);
    k_agg<<<ablk, 256>>>(rowptr, csr, tmp, dinv, b3, out_h);

    // classifier: logits = h3 @ Wc + bc
    k_gemm_cls<40><<<cblk, 160, SM40>>>(out_h, Wc, bc, out_logits, NN);
}

// round 5
// speedup vs baseline: 2.0071x; 1.0192x over previous
#include <cuda_runtime.h>
#include <cstdint>

#define NN 50000
#define NE 800000
#define NB 98        // scan blocks: 98*512 >= 50000
#define HA 25088     // first-half nodes (multiple of 128 and 64)
#define HB (NN - HA) // 24912 (multiple of 8)

// ---------------------------------------------------------------------------
// Scratch (static device arrays: allocation-free per harness rules)
// ---------------------------------------------------------------------------
__device__ float g_tmpA[NN * 128];
__device__ float g_tmpB[NN * 128];
__device__ float g_h[NN * 128];
__device__ float g_dinv[NN];
__device__ int   g_deg[NN];
__device__ int   g_rowptr[NN + 1];
__device__ int   g_cursor[NN];
__device__ int   g_csr[NE];
__device__ int   g_bsum[NB];

// ---------------------------------------------------------------------------
// Host-side stream/event context (host resources only; created at static init)
// ---------------------------------------------------------------------------
struct Ctx {
    cudaStream_t s;
    cudaEvent_t e[12];
    Ctx() {
        cudaStreamCreateWithFlags(&s, cudaStreamNonBlocking);
        for (int i = 0; i < 12; i++) cudaEventCreateWithFlags(&e[i], cudaEventDisableTiming);
    }
};
static Ctx g_ctx;

// ---------------------------------------------------------------------------
// degree / normalization
// ---------------------------------------------------------------------------
__global__ void k_deg_init(int* __restrict__ deg) {
    int i = blockIdx.x * blockDim.x + threadIdx.x;
    if (i < NN) deg[i] = 1;  // self-loop
}
__global__ void k_deg_count(const int* __restrict__ ei, int* __restrict__ deg) {
    int e = blockIdx.x * blockDim.x + threadIdx.x;
    if (e < NE) atomicAdd(&deg[ei[NE + e]], 1);
}
__global__ void k_dinv(const int* __restrict__ deg, float* __restrict__ dinv) {
    int i = blockIdx.x * blockDim.x + threadIdx.x;
    if (i < NN) dinv[i] = rsqrtf((float)deg[i]);
}

// ---------------------------------------------------------------------------
// CSR build: exclusive scan of edge counts (deg-1), then cursor fill.
// ---------------------------------------------------------------------------
__global__ void k_scan1(const int* __restrict__ deg, int* __restrict__ rowptr,
                        int* __restrict__ bsum) {
    __shared__ int s[512];
    int tid = threadIdx.x;
    int i = blockIdx.x * 512 + tid;
    int v = (i < NN) ? (deg[i] - 1) : 0;
    s[tid] = v;
    __syncthreads();
    for (int o = 1; o < 512; o <<= 1) {
        int t = (tid >= o) ? s[tid - o] : 0;
        __syncthreads();
        s[tid] += t;
        __syncthreads();
    }
    if (i < NN) rowptr[i] = s[tid] - v;
    if (tid == 511) bsum[blockIdx.x] = s[511];
}
__global__ void k_scan2(int* __restrict__ bsum) {
    if (threadIdx.x == 0 && blockIdx.x == 0) {
        int acc = 0;
        for (int i = 0; i < NB; i++) { int v = bsum[i]; bsum[i] = acc; acc += v; }
    }
}
__global__ void k_scan3(int* __restrict__ rowptr, const int* __restrict__ bsum,
                        int* __restrict__ cursor) {
    int i = blockIdx.x * 512 + threadIdx.x;
    if (i < NN) {
        int r = rowptr[i] + bsum[blockIdx.x];
        rowptr[i] = r;
        cursor[i] = r;
    }
    if (blockIdx.x == 0 && threadIdx.x == 0) rowptr[NN] = NE;
}
__global__ void k_fill(const int* __restrict__ ei, int* __restrict__ cursor,
                       int* __restrict__ csr) {
    int e = blockIdx.x * blockDim.x + threadIdx.x;
    if (e >= NE) return;
    int dst = ei[NE + e];
    int pos = atomicAdd(&cursor[dst], 1);
    csr[pos] = ei[e];
}

// ---------------------------------------------------------------------------
// GEMM 128x128: out[row] = (A[row] @ W) [* scale[row]]
// 512 threads, thread tile 8 rows x 4 cols, FFMA2 (fma.rn.f32x2) inner loop.
// ---------------------------------------------------------------------------
#define FFMA2(d, a, b) asm("fma.rn.f32x2 %0, %1, %2, %0;" : "+l"(d) : "l"(a), "l"(b))
#define PACK2(d, a)    asm("mov.b64 %0, {%1, %1};" : "=l"(d) : "f"(a))
union U64F2 { unsigned long long u; float2 f; };

static constexpr int GM_WS  = 0;
static constexpr int GM_AT  = 128 * 128;
static constexpr int GM_STG = 2 * 128 * 128;
static constexpr int GM_SMEM_FLOATS = 2 * 128 * 128 + 128 * 129;
static constexpr int GM_SMEM_BYTES  = GM_SMEM_FLOATS * 4;   // 197120

__global__ void __launch_bounds__(512, 1)
k_gemm128(const float* __restrict__ A, const float* __restrict__ W,
          const float* __restrict__ scale, float* __restrict__ out, int nrows) {
    extern __shared__ float sm[];
    float* Ws  = sm + GM_WS;
    float* At  = sm + GM_AT;
    float* Stg = sm + GM_STG;

    const int tid  = threadIdx.x;
    const int row0 = blockIdx.x * 128;

    {
        const float4* w4 = (const float4*)W;
        float4* s4 = (float4*)Ws;
        for (int i = tid; i < 4096; i += 512) s4[i] = w4[i];
    }
    for (int i = tid; i < 4096; i += 512) {
        int r = i >> 5, kq = i & 31;
        int grow = row0 + r;
        float4 f = make_float4(0.f, 0.f, 0.f, 0.f);
        if (grow < nrows) f = ((const float4*)A)[(size_t)grow * 32 + kq];
        float* p = Stg + r * 129 + kq * 4;
        p[0] = f.x; p[1] = f.y; p[2] = f.z; p[3] = f.w;
    }
    __syncthreads();
    for (int i = tid; i < 16384; i += 512) {
        int r = i & 127, k = i >> 7;
        At[k * 128 + r] = Stg[r * 129 + k];
    }
    __syncthreads();

    const int tc = tid & 31;
    const int tr = tid >> 5;

    unsigned long long acc[8][2];
#pragma unroll
    for (int i = 0; i < 8; i++) { acc[i][0] = 0ull; acc[i][1] = 0ull; }

    const float* Wp = Ws + 4 * tc;
    const float* Ap = At + 8 * tr;

#pragma unroll 4
    for (int k = 0; k < 128; k++) {
        ulonglong2 wv = *(const ulonglong2*)(Wp + k * 128);
        float4 a0 = *(const float4*)(Ap + k * 128);
        float4 a1 = *(const float4*)(Ap + k * 128 + 4);
        unsigned long long p0, p1, p2, p3, p4, p5, p6, p7;
        PACK2(p0, a0.x); PACK2(p1, a0.y); PACK2(p2, a0.z); PACK2(p3, a0.w);
        PACK2(p4, a1.x); PACK2(p5, a1.y); PACK2(p6, a1.z); PACK2(p7, a1.w);
        FFMA2(acc[0][0], p0, wv.x); FFMA2(acc[0][1], p0, wv.y);
        FFMA2(acc[1][0], p1, wv.x); FFMA2(acc[1][1], p1, wv.y);
        FFMA2(acc[2][0], p2, wv.x); FFMA2(acc[2][1], p2, wv.y);
        FFMA2(acc[3][0], p3, wv.x); FFMA2(acc[3][1], p3, wv.y);
        FFMA2(acc[4][0], p4, wv.x); FFMA2(acc[4][1], p4, wv.y);
        FFMA2(acc[5][0], p5, wv.x); FFMA2(acc[5][1], p5, wv.y);
        FFMA2(acc[6][0], p6, wv.x); FFMA2(acc[6][1], p6, wv.y);
        FFMA2(acc[7][0], p7, wv.x); FFMA2(acc[7][1], p7, wv.y);
    }

#pragma unroll
    for (int i = 0; i < 8; i++) {
        int row = row0 + 8 * tr + i;
        if (row < nrows) {
            float s = scale ? scale[row] : 1.0f;
            U64F2 u0, u1;
            u0.u = acc[i][0];
            u1.u = acc[i][1];
            float4 v = make_float4(u0.f.x * s, u0.f.y * s, u1.f.x * s, u1.f.y * s);
            *(float4*)(out + (size_t)row * 128 + 4 * tc) = v;
        }
    }
}

// ---------------------------------------------------------------------------
// Aggregate (CSR gather) over node range [n0, n0+ncnt):
//   edinv == null: out[n] = relu(dinv[n]*(tmp[n] + sum tmp[src]) + bias)   (tmp pre-scaled)
//   edinv != null: out[n] = relu(dinv[n]*(edinv[n]*tmp[n] + sum edinv[s]*tmp[s]) + bias)
// One warp per node; lane owns a float4 slice.
// ---------------------------------------------------------------------------
__global__ void k_agg(const int* __restrict__ rowptr, const int* __restrict__ csr,
                      const float* __restrict__ tmp, const float* __restrict__ dinv,
                      const float* __restrict__ edinv, const float* __restrict__ bias,
                      float* __restrict__ out, int n0, int ncnt) {
    int wi = (blockIdx.x * blockDim.x + threadIdx.x) >> 5;
    if (wi >= ncnt) return;
    int w = n0 + wi;
    int lane = threadIdx.x & 31;
    const float4* t4 = (const float4*)tmp;

    float4 self = t4[(size_t)w * 32 + lane];
    float se = edinv ? edinv[w] : 1.0f;
    float4 a = make_float4(self.x * se, self.y * se, self.z * se, self.w * se);
    float4 a2 = make_float4(0.f, 0.f, 0.f, 0.f);

    int e   = __ldg(rowptr + w);
    int end = __ldg(rowptr + w + 1);
    if (edinv) {
        for (; e + 1 < end; e += 2) {
            int s0 = __ldg(csr + e);
            int s1 = __ldg(csr + e + 1);
            float e0 = __ldg(edinv + s0), e1 = __ldg(edinv + s1);
            float4 v0 = t4[(size_t)s0 * 32 + lane];
            float4 v1 = t4[(size_t)s1 * 32 + lane];
            a.x = fmaf(v0.x, e0, a.x);  a.y = fmaf(v0.y, e0, a.y);
            a.z = fmaf(v0.z, e0, a.z);  a.w = fmaf(v0.w, e0, a.w);
            a2.x = fmaf(v1.x, e1, a2.x); a2.y = fmaf(v1.y, e1, a2.y);
            a2.z = fmaf(v1.z, e1, a2.z); a2.w = fmaf(v1.w, e1, a2.w);
        }
        if (e < end) {
            int s0 = __ldg(csr + e);
            float e0 = __ldg(edinv + s0);
            float4 v0 = t4[(size_t)s0 * 32 + lane];
            a.x = fmaf(v0.x, e0, a.x); a.y = fmaf(v0.y, e0, a.y);
            a.z = fmaf(v0.z, e0, a.z); a.w = fmaf(v0.w, e0, a.w);
        }
    } else {
        for (; e + 1 < end; e += 2) {
            int s0 = __ldg(csr + e);
            int s1 = __ldg(csr + e + 1);
            float4 v0 = t4[(size_t)s0 * 32 + lane];
            float4 v1 = t4[(size_t)s1 * 32 + lane];
            a.x += v0.x;  a.y += v0.y;  a.z += v0.z;  a.w += v0.w;
            a2.x += v1.x; a2.y += v1.y; a2.z += v1.z; a2.w += v1.w;
        }
        if (e < end) {
            int s0 = __ldg(csr + e);
            float4 v0 = t4[(size_t)s0 * 32 + lane];
            a.x += v0.x; a.y += v0.y; a.z += v0.z; a.w += v0.w;
        }
    }
    a.x += a2.x; a.y += a2.y; a.z += a2.z; a.w += a2.w;

    float sc = dinv[w];
    float4 b = ((const float4*)bias)[lane];
    a.x = fmaxf(fmaf(a.x, sc, b.x), 0.0f);
    a.y = fmaxf(fmaf(a.y, sc, b.y), 0.0f);
    a.z = fmaxf(fmaf(a.z, sc, b.z), 0.0f);
    a.w = fmaxf(fmaf(a.w, sc, b.w), 0.0f);
    ((float4*)out)[(size_t)w * 32 + lane] = a;
}

// ---------------------------------------------------------------------------
// Classifier SIMT GEMM (BN=40), FFMA2 path.
// ---------------------------------------------------------------------------
template <int BN>
__global__ void k_gemm_cls(const float* __restrict__ A, const float* __restrict__ W,
                           const float* __restrict__ bias,
                           float* __restrict__ out0, int nrows) {
    constexpr int BM = 64;
    constexpr int TX = BN / 4;
    constexpr int TY = BM / 4;
    constexpr int NT = TX * TY;

    extern __shared__ float fsm[];
    float*  Ws = fsm;
    float2* Ad = (float2*)(fsm + 128 * BN);
    float*  As = (float*)(Ad + 128 * BM);

    const int tid  = threadIdx.x;
    const int row0 = blockIdx.x * BM;

    for (int idx = tid; idx < 128 * BN; idx += NT) Ws[idx] = W[idx];
    for (int idx = tid; idx < BM * 128; idx += NT) {
        int r = idx >> 7, k = idx & 127;
        int gr = row0 + r;
        As[r * 129 + k] = (gr < nrows) ? A[(size_t)gr * 128 + k] : 0.0f;
    }
    __syncthreads();
    for (int idx = tid; idx < 128 * BM; idx += NT) {
        int r = idx % BM, k = idx / BM;
        float v = As[r * 129 + k];
        Ad[idx] = make_float2(v, v);
    }
    __syncthreads();

    const int tc = tid % TX, tr = tid / TX;
    unsigned long long acc[4][2];
#pragma unroll
    for (int r = 0; r < 4; r++) { acc[r][0] = 0ull; acc[r][1] = 0ull; }

    const float2* adp = Ad + 4 * tr;
    const float*  wsp = Ws + 4 * tc;

#pragma unroll 8
    for (int k = 0; k < 128; k++) {
        ulonglong2 av0 = *(const ulonglong2*)(adp + (size_t)k * BM);
        ulonglong2 av1 = *(const ulonglong2*)(adp + (size_t)k * BM + 2);
        ulonglong2 wv  = *(const ulonglong2*)(wsp + (size_t)k * BN);
        FFMA2(acc[0][0], av0.x, wv.x); FFMA2(acc[0][1], av0.x, wv.y);
        FFMA2(acc[1][0], av0.y, wv.x); FFMA2(acc[1][1], av0.y, wv.y);
        FFMA2(acc[2][0], av1.x, wv.x); FFMA2(acc[2][1], av1.x, wv.y);
        FFMA2(acc[3][0], av1.y, wv.x); FFMA2(acc[3][1], av1.y, wv.y);
    }

#pragma unroll
    for (int r = 0; r < 4; r++) {
        int row = row0 + 4 * tr + r;
        if (row >= nrows) break;
        U64F2 u0, u1;
        u0.u = acc[r][0];
        u1.u = acc[r][1];
        float4 v = make_float4(u0.f.x + bias[4 * tc + 0], u0.f.y + bias[4 * tc + 1],
                               u1.f.x + bias[4 * tc + 2], u1.f.y + bias[4 * tc + 3]);
        *(float4*)(out0 + (size_t)row * BN + 4 * tc) = v;
    }
}

// ---------------------------------------------------------------------------
extern "C" void kernel_launch(void* const* d_in, const int* in_sizes, int n_in,
                              void* d_out, int out_size) {
    const float* x  = (const float*)d_in[0];
    const int*   ei = (const int*)d_in[1];
    const float* W1 = (const float*)d_in[2];
    const float* b1 = (const float*)d_in[3];
    const float* W2 = (const float*)d_in[4];
    const float* b2 = (const float*)d_in[5];
    const float* W3 = (const float*)d_in[6];
    const float* b3 = (const float*)d_in[7];
    const float* Wc = (const float*)d_in[8];
    const float* bc = (const float*)d_in[9];

    float* out_logits = (float*)d_out;                    // [NN,40]
    float* out_h      = (float*)d_out + (size_t)NN * 40;  // [NN,128]

    float *tmpA, *tmpB, *h, *dinv;
    int *deg, *rowptr, *cursor, *csr, *bsum;
    cudaGetSymbolAddress((void**)&tmpA,   g_tmpA);
    cudaGetSymbolAddress((void**)&tmpB,   g_tmpB);
    cudaGetSymbolAddress((void**)&h,      g_h);
    cudaGetSymbolAddress((void**)&dinv,   g_dinv);
    cudaGetSymbolAddress((void**)&deg,    g_deg);
    cudaGetSymbolAddress((void**)&rowptr, g_rowptr);
    cudaGetSymbolAddress((void**)&cursor, g_cursor);
    cudaGetSymbolAddress((void**)&csr,    g_csr);
    cudaGetSymbolAddress((void**)&bsum,   g_bsum);

    const int SM40 = 128 * 40 * 4 + 128 * 64 * 8 + 64 * 129 * 4;
    cudaFuncSetAttribute(k_gemm128, cudaFuncAttributeMaxDynamicSharedMemorySize, GM_SMEM_BYTES);
    cudaFuncSetAttribute(k_gemm_cls<40>, cudaFuncAttributeMaxDynamicSharedMemorySize, SM40);

    cudaStream_t S = g_ctx.s;
    cudaEvent_t* E = g_ctx.e;

    // fork side stream off the capture (main) stream
    cudaEventRecord(E[0], 0);
    cudaStreamWaitEvent(S, E[0], 0);

    // ---- side stream: normalization + CSR build (hidden behind GEMM1) ----
    k_deg_init<<<(NN + 255) / 256, 256, 0, S>>>(deg);
    k_deg_count<<<(NE + 255) / 256, 256, 0, S>>>(ei, deg);
    k_dinv<<<(NN + 255) / 256, 256, 0, S>>>(deg, dinv);
    k_scan1<<<NB, 512, 0, S>>>(deg, rowptr, bsum);
    k_scan2<<<1, 32, 0, S>>>(bsum);
    k_scan3<<<NB, 512, 0, S>>>(rowptr, bsum, cursor);
    k_fill<<<(NE + 255) / 256, 256, 0, S>>>(ei, cursor, csr);
    cudaEventRecord(E[1], S);   // CSR + dinv ready

    // ---- main: layer 1 GEMM -> tmpA (unscaled; no dinv dependency) ----
    k_gemm128<<<(NN + 127) / 128, 512, GM_SMEM_BYTES>>>(x, W1, nullptr, tmpA, NN);

    // agg layer 1 reads tmpA (dinv[src] per edge), writes h
    cudaStreamWaitEvent(0, E[1], 0);
    k_agg<<<HA / 8, 256>>>(rowptr, csr, tmpA, dinv, dinv, b1, h, 0, HA);
    cudaEventRecord(E[2], 0);   // h rows [0,HA) ready
    k_agg<<<HB / 8, 256>>>(rowptr, csr, tmpA, dinv, dinv, b1, h, HA, HB);

    // side: GEMM2-A (reads h[0:HA), writes tmpB) overlaps agg1-B (reads tmpA)
    cudaStreamWaitEvent(S, E[2], 0);
    k_gemm128<<<HA / 128, 512, GM_SMEM_BYTES, S>>>(h, W2, dinv, tmpB, HA);
    cudaEventRecord(E[3], S);
    // main: GEMM2-B
    k_gemm128<<<(HB + 127) / 128, 512, GM_SMEM_BYTES>>>(h + (size_t)HA * 128, W2,
                                                        dinv + HA, tmpB + (size_t)HA * 128, HB);
    cudaStreamWaitEvent(0, E[3], 0);
    // agg layer 2 reads tmpB, writes h
    k_agg<<<HA / 8, 256>>>(rowptr, csr, tmpB, dinv, nullptr, b2, h, 0, HA);
    cudaEventRecord(E[4], 0);
    k_agg<<<HB / 8, 256>>>(rowptr, csr, tmpB, dinv, nullptr, b2, h, HA, HB);

    // side: GEMM3-A (reads h[0:HA), writes tmpA) overlaps agg2-B (reads tmpB)
    cudaStreamWaitEvent(S, E[4], 0);
    k_gemm128<<<HA / 128, 512, GM_SMEM_BYTES, S>>>(h, W3, dinv, tmpA, HA);
    cudaEventRecord(E[5], S);
    // main: GEMM3-B
    k_gemm128<<<(HB + 127) / 128, 512, GM_SMEM_BYTES>>>(h + (size_t)HA * 128, W3,
                                                        dinv + HA, tmpA + (size_t)HA * 128, HB);
    cudaStreamWaitEvent(0, E[5], 0);
    // agg layer 3 reads tmpA, writes out_h
    k_agg<<<HA / 8, 256>>>(rowptr, csr, tmpA, dinv, nullptr, b3, out_h, 0, HA);
    cudaEventRecord(E[6], 0);
    k_agg<<<HB / 8, 256>>>(rowptr, csr, tmpA, dinv, nullptr, b3, out_h, HA, HB);

    // side: classifier-A (reads out_h[0:HA)) overlaps agg3-B (writes out_h[HA:))
    cudaStreamWaitEvent(S, E[6], 0);
    k_gemm_cls<40><<<HA / 64, 160, SM40, S>>>(out_h, Wc, bc, out_logits, HA);
    cudaEventRecord(E[7], S);
    // main: classifier-B
    k_gemm_cls<40><<<(HB + 63) / 64, 160, SM40>>>(out_h + (size_t)HA * 128, Wc, bc,
                                                  out_logits + (size_t)HA * 40, HB);
    // join side stream back into main before capture ends
    cudaStreamWaitEvent(0, E[7], 0);
}

// round 6
// speedup vs baseline: 2.1423x; 1.0673x over previous
#include <cuda_runtime.h>
#include <cuda_fp16.h>
#include <cstdint>

#define NN 50000
#define NE 800000
#define NB 98        // scan blocks: 98*512 >= 50000
#define HA 25088     // first-half nodes (multiple of 128 and 64)
#define HB (NN - HA) // 24912 (multiple of 8)

// ---------------------------------------------------------------------------
// Scratch (static device arrays: allocation-free per harness rules)
// ---------------------------------------------------------------------------
__device__ __half g_tmpA[NN * 128];
__device__ __half g_tmpB[NN * 128];
__device__ float  g_h[NN * 128];
__device__ float  g_dinv[NN];
__device__ int    g_deg[NN];
__device__ int    g_rowptr[NN + 1];
__device__ int    g_cursor[NN];
__device__ int    g_csr[NE];
__device__ int    g_bsum[NB];

// ---------------------------------------------------------------------------
// Host-side stream/event context (host resources only; created at static init)
// ---------------------------------------------------------------------------
struct Ctx {
    cudaStream_t s;
    cudaEvent_t e[12];
    Ctx() {
        cudaStreamCreateWithFlags(&s, cudaStreamNonBlocking);
        for (int i = 0; i < 12; i++) cudaEventCreateWithFlags(&e[i], cudaEventDisableTiming);
    }
};
static Ctx g_ctx;

// ---------------------------------------------------------------------------
// degree / normalization
// ---------------------------------------------------------------------------
__global__ void k_deg_init(int* __restrict__ deg) {
    int i = blockIdx.x * blockDim.x + threadIdx.x;
    if (i < NN) deg[i] = 1;  // self-loop
}
__global__ void k_deg_count(const int* __restrict__ ei, int* __restrict__ deg) {
    int e = blockIdx.x * blockDim.x + threadIdx.x;
    if (e < NE) atomicAdd(&deg[ei[NE + e]], 1);
}
__global__ void k_dinv(const int* __restrict__ deg, float* __restrict__ dinv) {
    int i = blockIdx.x * blockDim.x + threadIdx.x;
    if (i < NN) dinv[i] = rsqrtf((float)deg[i]);
}

// ---------------------------------------------------------------------------
// CSR build: exclusive scan of edge counts (deg-1), then cursor fill.
// ---------------------------------------------------------------------------
__global__ void k_scan1(const int* __restrict__ deg, int* __restrict__ rowptr,
                        int* __restrict__ bsum) {
    __shared__ int s[512];
    int tid = threadIdx.x;
    int i = blockIdx.x * 512 + tid;
    int v = (i < NN) ? (deg[i] - 1) : 0;
    s[tid] = v;
    __syncthreads();
    for (int o = 1; o < 512; o <<= 1) {
        int t = (tid >= o) ? s[tid - o] : 0;
        __syncthreads();
        s[tid] += t;
        __syncthreads();
    }
    if (i < NN) rowptr[i] = s[tid] - v;
    if (tid == 511) bsum[blockIdx.x] = s[511];
}
__global__ void k_scan2(int* __restrict__ bsum) {
    if (threadIdx.x == 0 && blockIdx.x == 0) {
        int acc = 0;
        for (int i = 0; i < NB; i++) { int v = bsum[i]; bsum[i] = acc; acc += v; }
    }
}
__global__ void k_scan3(int* __restrict__ rowptr, const int* __restrict__ bsum,
                        int* __restrict__ cursor) {
    int i = blockIdx.x * 512 + threadIdx.x;
    if (i < NN) {
        int r = rowptr[i] + bsum[blockIdx.x];
        rowptr[i] = r;
        cursor[i] = r;
    }
    if (blockIdx.x == 0 && threadIdx.x == 0) rowptr[NN] = NE;
}
__global__ void k_fill(const int* __restrict__ ei, int* __restrict__ cursor,
                       int* __restrict__ csr) {
    int e = blockIdx.x * blockDim.x + threadIdx.x;
    if (e >= NE) return;
    int dst = ei[NE + e];
    int pos = atomicAdd(&cursor[dst], 1);
    csr[pos] = ei[e];
}

// ---------------------------------------------------------------------------
// GEMM 128x128: out[row] = fp16( (A[row] @ W) [* scale[row]] )
// 512 threads, thread tile 8 rows x 4 cols, FFMA2 (fma.rn.f32x2) inner loop.
// ---------------------------------------------------------------------------
#define FFMA2(d, a, b) asm("fma.rn.f32x2 %0, %1, %2, %0;" : "+l"(d) : "l"(a), "l"(b))
#define PACK2(d, a)    asm("mov.b64 %0, {%1, %1};" : "=l"(d) : "f"(a))
union U64F2 { unsigned long long u; float2 f; };

static constexpr int GM_WS  = 0;
static constexpr int GM_AT  = 128 * 128;
static constexpr int GM_STG = 2 * 128 * 128;
static constexpr int GM_SMEM_FLOATS = 2 * 128 * 128 + 128 * 129;
static constexpr int GM_SMEM_BYTES  = GM_SMEM_FLOATS * 4;   // 197120

__global__ void __launch_bounds__(512, 1)
k_gemm128(const float* __restrict__ A, const float* __restrict__ W,
          const float* __restrict__ scale, __half* __restrict__ out, int nrows) {
    extern __shared__ float sm[];
    float* Ws  = sm + GM_WS;
    float* At  = sm + GM_AT;
    float* Stg = sm + GM_STG;

    const int tid  = threadIdx.x;
    const int row0 = blockIdx.x * 128;

    {
        const float4* w4 = (const float4*)W;
        float4* s4 = (float4*)Ws;
        for (int i = tid; i < 4096; i += 512) s4[i] = w4[i];
    }
    for (int i = tid; i < 4096; i += 512) {
        int r = i >> 5, kq = i & 31;
        int grow = row0 + r;
        float4 f = make_float4(0.f, 0.f, 0.f, 0.f);
        if (grow < nrows) f = ((const float4*)A)[(size_t)grow * 32 + kq];
        float* p = Stg + r * 129 + kq * 4;
        p[0] = f.x; p[1] = f.y; p[2] = f.z; p[3] = f.w;
    }
    __syncthreads();
    for (int i = tid; i < 16384; i += 512) {
        int r = i & 127, k = i >> 7;
        At[k * 128 + r] = Stg[r * 129 + k];
    }
    __syncthreads();

    const int tc = tid & 31;
    const int tr = tid >> 5;

    unsigned long long acc[8][2];
#pragma unroll
    for (int i = 0; i < 8; i++) { acc[i][0] = 0ull; acc[i][1] = 0ull; }

    const float* Wp = Ws + 4 * tc;
    const float* Ap = At + 8 * tr;

#pragma unroll 4
    for (int k = 0; k < 128; k++) {
        ulonglong2 wv = *(const ulonglong2*)(Wp + k * 128);
        float4 a0 = *(const float4*)(Ap + k * 128);
        float4 a1 = *(const float4*)(Ap + k * 128 + 4);
        unsigned long long p0, p1, p2, p3, p4, p5, p6, p7;
        PACK2(p0, a0.x); PACK2(p1, a0.y); PACK2(p2, a0.z); PACK2(p3, a0.w);
        PACK2(p4, a1.x); PACK2(p5, a1.y); PACK2(p6, a1.z); PACK2(p7, a1.w);
        FFMA2(acc[0][0], p0, wv.x); FFMA2(acc[0][1], p0, wv.y);
        FFMA2(acc[1][0], p1, wv.x); FFMA2(acc[1][1], p1, wv.y);
        FFMA2(acc[2][0], p2, wv.x); FFMA2(acc[2][1], p2, wv.y);
        FFMA2(acc[3][0], p3, wv.x); FFMA2(acc[3][1], p3, wv.y);
        FFMA2(acc[4][0], p4, wv.x); FFMA2(acc[4][1], p4, wv.y);
        FFMA2(acc[5][0], p5, wv.x); FFMA2(acc[5][1], p5, wv.y);
        FFMA2(acc[6][0], p6, wv.x); FFMA2(acc[6][1], p6, wv.y);
        FFMA2(acc[7][0], p7, wv.x); FFMA2(acc[7][1], p7, wv.y);
    }

#pragma unroll
    for (int i = 0; i < 8; i++) {
        int row = row0 + 8 * tr + i;
        if (row < nrows) {
            float s = scale ? scale[row] : 1.0f;
            U64F2 u0, u1;
            u0.u = acc[i][0];
            u1.u = acc[i][1];
            __half2 h0 = __floats2half2_rn(u0.f.x * s, u0.f.y * s);
            __half2 h1 = __floats2half2_rn(u1.f.x * s, u1.f.y * s);
            uint2 pk = make_uint2(*(uint32_t*)&h0, *(uint32_t*)&h1);
            ((uint2*)(out + (size_t)row * 128))[tc] = pk;   // 8B per thread-row
        }
    }
}

// ---------------------------------------------------------------------------
// Aggregate (CSR gather of fp16 rows) over node range [n0, n0+ncnt):
//   edinv == null: out[n] = relu(dinv[n]*(tmp[n] + sum tmp[src]) + bias)
//   edinv != null: out[n] = relu(dinv[n]*(edinv[n]*tmp[n] + sum edinv[s]*tmp[s]) + bias)
// One warp per node; lane owns 4 halves (8B) per row. fp32 accumulation.
// ---------------------------------------------------------------------------
__device__ __forceinline__ float4 h4f4(uint2 r) {
    __half2 a = *(__half2*)&r.x, b = *(__half2*)&r.y;
    float2 fa = __half22float2(a), fb = __half22float2(b);
    return make_float4(fa.x, fa.y, fb.x, fb.y);
}

__global__ void k_agg(const int* __restrict__ rowptr, const int* __restrict__ csr,
                      const __half* __restrict__ tmp, const float* __restrict__ dinv,
                      const float* __restrict__ edinv, const float* __restrict__ bias,
                      float* __restrict__ out, int n0, int ncnt) {
    int wi = (blockIdx.x * blockDim.x + threadIdx.x) >> 5;
    if (wi >= ncnt) return;
    int w = n0 + wi;
    int lane = threadIdx.x & 31;
    const uint2* t2 = (const uint2*)tmp;   // 32 uint2 per 128-half row

    float4 self = h4f4(t2[(size_t)w * 32 + lane]);
    float se = edinv ? edinv[w] : 1.0f;
    float4 a = make_float4(self.x * se, self.y * se, self.z * se, self.w * se);
    float4 a2 = make_float4(0.f, 0.f, 0.f, 0.f);

    int e   = __ldg(rowptr + w);
    int end = __ldg(rowptr + w + 1);
    if (edinv) {
        for (; e + 1 < end; e += 2) {
            int s0 = __ldg(csr + e);
            int s1 = __ldg(csr + e + 1);
            float e0 = __ldg(edinv + s0), e1 = __ldg(edinv + s1);
            float4 v0 = h4f4(t2[(size_t)s0 * 32 + lane]);
            float4 v1 = h4f4(t2[(size_t)s1 * 32 + lane]);
            a.x = fmaf(v0.x, e0, a.x);  a.y = fmaf(v0.y, e0, a.y);
            a.z = fmaf(v0.z, e0, a.z);  a.w = fmaf(v0.w, e0, a.w);
            a2.x = fmaf(v1.x, e1, a2.x); a2.y = fmaf(v1.y, e1, a2.y);
            a2.z = fmaf(v1.z, e1, a2.z); a2.w = fmaf(v1.w, e1, a2.w);
        }
        if (e < end) {
            int s0 = __ldg(csr + e);
            float e0 = __ldg(edinv + s0);
            float4 v0 = h4f4(t2[(size_t)s0 * 32 + lane]);
            a.x = fmaf(v0.x, e0, a.x); a.y = fmaf(v0.y, e0, a.y);
            a.z = fmaf(v0.z, e0, a.z); a.w = fmaf(v0.w, e0, a.w);
        }
    } else {
        for (; e + 1 < end; e += 2) {
            int s0 = __ldg(csr + e);
            int s1 = __ldg(csr + e + 1);
            float4 v0 = h4f4(t2[(size_t)s0 * 32 + lane]);
            float4 v1 = h4f4(t2[(size_t)s1 * 32 + lane]);
            a.x += v0.x;  a.y += v0.y;  a.z += v0.z;  a.w += v0.w;
            a2.x += v1.x; a2.y += v1.y; a2.z += v1.z; a2.w += v1.w;
        }
        if (e < end) {
            int s0 = __ldg(csr + e);
            float4 v0 = h4f4(t2[(size_t)s0 * 32 + lane]);
            a.x += v0.x; a.y += v0.y; a.z += v0.z; a.w += v0.w;
        }
    }
    a.x += a2.x; a.y += a2.y; a.z += a2.z; a.w += a2.w;

    float sc = dinv[w];
    float4 b = ((const float4*)bias)[lane];
    a.x = fmaxf(fmaf(a.x, sc, b.x), 0.0f);
    a.y = fmaxf(fmaf(a.y, sc, b.y), 0.0f);
    a.z = fmaxf(fmaf(a.z, sc, b.z), 0.0f);
    a.w = fmaxf(fmaf(a.w, sc, b.w), 0.0f);
    ((float4*)out)[(size_t)w * 32 + lane] = a;
}

// ---------------------------------------------------------------------------
// Classifier SIMT GEMM (BN=40), FFMA2 path.
// ---------------------------------------------------------------------------
template <int BN>
__global__ void k_gemm_cls(const float* __restrict__ A, const float* __restrict__ W,
                           const float* __restrict__ bias,
                           float* __restrict__ out0, int nrows) {
    constexpr int BM = 64;
    constexpr int TX = BN / 4;
    constexpr int TY = BM / 4;
    constexpr int NT = TX * TY;

    extern __shared__ float fsm[];
    float*  Ws = fsm;
    float2* Ad = (float2*)(fsm + 128 * BN);
    float*  As = (float*)(Ad + 128 * BM);

    const int tid  = threadIdx.x;
    const int row0 = blockIdx.x * BM;

    for (int idx = tid; idx < 128 * BN; idx += NT) Ws[idx] = W[idx];
    for (int idx = tid; idx < BM * 128; idx += NT) {
        int r = idx >> 7, k = idx & 127;
        int gr = row0 + r;
        As[r * 129 + k] = (gr < nrows) ? A[(size_t)gr * 128 + k] : 0.0f;
    }
    __syncthreads();
    for (int idx = tid; idx < 128 * BM; idx += NT) {
        int r = idx % BM, k = idx / BM;
        float v = As[r * 129 + k];
        Ad[idx] = make_float2(v, v);
    }
    __syncthreads();

    const int tc = tid % TX, tr = tid / TX;
    unsigned long long acc[4][2];
#pragma unroll
    for (int r = 0; r < 4; r++) { acc[r][0] = 0ull; acc[r][1] = 0ull; }

    const float2* adp = Ad + 4 * tr;
    const float*  wsp = Ws + 4 * tc;

#pragma unroll 8
    for (int k = 0; k < 128; k++) {
        ulonglong2 av0 = *(const ulonglong2*)(adp + (size_t)k * BM);
        ulonglong2 av1 = *(const ulonglong2*)(adp + (size_t)k * BM + 2);
        ulonglong2 wv  = *(const ulonglong2*)(wsp + (size_t)k * BN);
        FFMA2(acc[0][0], av0.x, wv.x); FFMA2(acc[0][1], av0.x, wv.y);
        FFMA2(acc[1][0], av0.y, wv.x); FFMA2(acc[1][1], av0.y, wv.y);
        FFMA2(acc[2][0], av1.x, wv.x); FFMA2(acc[2][1], av1.x, wv.y);
        FFMA2(acc[3][0], av1.y, wv.x); FFMA2(acc[3][1], av1.y, wv.y);
    }

#pragma unroll
    for (int r = 0; r < 4; r++) {
        int row = row0 + 4 * tr + r;
        if (row >= nrows) break;
        U64F2 u0, u1;
        u0.u = acc[r][0];
        u1.u = acc[r][1];
        float4 v = make_float4(u0.f.x + bias[4 * tc + 0], u0.f.y + bias[4 * tc + 1],
                               u1.f.x + bias[4 * tc + 2], u1.f.y + bias[4 * tc + 3]);
        *(float4*)(out0 + (size_t)row * BN + 4 * tc) = v;
    }
}

// ---------------------------------------------------------------------------
extern "C" void kernel_launch(void* const* d_in, const int* in_sizes, int n_in,
                              void* d_out, int out_size) {
    const float* x  = (const float*)d_in[0];
    const int*   ei = (const int*)d_in[1];
    const float* W1 = (const float*)d_in[2];
    const float* b1 = (const float*)d_in[3];
    const float* W2 = (const float*)d_in[4];
    const float* b2 = (const float*)d_in[5];
    const float* W3 = (const float*)d_in[6];
    const float* b3 = (const float*)d_in[7];
    const float* Wc = (const float*)d_in[8];
    const float* bc = (const float*)d_in[9];

    float* out_logits = (float*)d_out;                    // [NN,40]
    float* out_h      = (float*)d_out + (size_t)NN * 40;  // [NN,128]

    __half *tmpA, *tmpB;
    float *h, *dinv;
    int *deg, *rowptr, *cursor, *csr, *bsum;
    cudaGetSymbolAddress((void**)&tmpA,   g_tmpA);
    cudaGetSymbolAddress((void**)&tmpB,   g_tmpB);
    cudaGetSymbolAddress((void**)&h,      g_h);
    cudaGetSymbolAddress((void**)&dinv,   g_dinv);
    cudaGetSymbolAddress((void**)&deg,    g_deg);
    cudaGetSymbolAddress((void**)&rowptr, g_rowptr);
    cudaGetSymbolAddress((void**)&cursor, g_cursor);
    cudaGetSymbolAddress((void**)&csr,    g_csr);
    cudaGetSymbolAddress((void**)&bsum,   g_bsum);

    const int SM40 = 128 * 40 * 4 + 128 * 64 * 8 + 64 * 129 * 4;
    cudaFuncSetAttribute(k_gemm128, cudaFuncAttributeMaxDynamicSharedMemorySize, GM_SMEM_BYTES);
    cudaFuncSetAttribute(k_gemm_cls<40>, cudaFuncAttributeMaxDynamicSharedMemorySize, SM40);

    cudaStream_t S = g_ctx.s;
    cudaEvent_t* E = g_ctx.e;

    // fork side stream off the capture (main) stream
    cudaEventRecord(E[0], 0);
    cudaStreamWaitEvent(S, E[0], 0);

    // ---- side stream: normalization + CSR build (hidden behind GEMM1) ----
    k_deg_init<<<(NN + 255) / 256, 256, 0, S>>>(deg);
    k_deg_count<<<(NE + 255) / 256, 256, 0, S>>>(ei, deg);
    k_dinv<<<(NN + 255) / 256, 256, 0, S>>>(deg, dinv);
    k_scan1<<<NB, 512, 0, S>>>(deg, rowptr, bsum);
    k_scan2<<<1, 32, 0, S>>>(bsum);
    k_scan3<<<NB, 512, 0, S>>>(rowptr, bsum, cursor);
    k_fill<<<(NE + 255) / 256, 256, 0, S>>>(ei, cursor, csr);
    cudaEventRecord(E[1], S);   // CSR + dinv ready

    // ---- main: layer 1 GEMM -> tmpA (unscaled; no dinv dependency) ----
    k_gemm128<<<(NN + 127) / 128, 512, GM_SMEM_BYTES>>>(x, W1, nullptr, tmpA, NN);

    // agg layer 1 reads tmpA (dinv[src] per edge), writes h
    cudaStreamWaitEvent(0, E[1], 0);
    k_agg<<<HA / 8, 256>>>(rowptr, csr, tmpA, dinv, dinv, b1, h, 0, HA);
    cudaEventRecord(E[2], 0);   // h rows [0,HA) ready
    k_agg<<<HB / 8, 256>>>(rowptr, csr, tmpA, dinv, dinv, b1, h, HA, HB);

    // side: GEMM2-A (reads h[0:HA), writes tmpB) overlaps agg1-B (reads tmpA)
    cudaStreamWaitEvent(S, E[2], 0);
    k_gemm128<<<HA / 128, 512, GM_SMEM_BYTES, S>>>(h, W2, dinv, tmpB, HA);
    cudaEventRecord(E[3], S);
    // main: GEMM2-B
    k_gemm128<<<(HB + 127) / 128, 512, GM_SMEM_BYTES>>>(h + (size_t)HA * 128, W2,
                                                        dinv + HA, tmpB + (size_t)HA * 128, HB);
    cudaStreamWaitEvent(0, E[3], 0);
    // agg layer 2 reads tmpB, writes h
    k_agg<<<HA / 8, 256>>>(rowptr, csr, tmpB, dinv, nullptr, b2, h, 0, HA);
    cudaEventRecord(E[4], 0);
    k_agg<<<HB / 8, 256>>>(rowptr, csr, tmpB, dinv, nullptr, b2, h, HA, HB);

    // side: GEMM3-A (reads h[0:HA), writes tmpA) overlaps agg2-B (reads tmpB)
    cudaStreamWaitEvent(S, E[4], 0);
    k_gemm128<<<HA / 128, 512, GM_SMEM_BYTES, S>>>(h, W3, dinv, tmpA, HA);
    cudaEventRecord(E[5], S);
    // main: GEMM3-B
    k_gemm128<<<(HB + 127) / 128, 512, GM_SMEM_BYTES>>>(h + (size_t)HA * 128, W3,
                                                        dinv + HA, tmpA + (size_t)HA * 128, HB);
    cudaStreamWaitEvent(0, E[5], 0);
    // agg layer 3 reads tmpA, writes out_h
    k_agg<<<HA / 8, 256>>>(rowptr, csr, tmpA, dinv, nullptr, b3, out_h, 0, HA);
    cudaEventRecord(E[6], 0);
    k_agg<<<HB / 8, 256>>>(rowptr, csr, tmpA, dinv, nullptr, b3, out_h, HA, HB);

    // side: classifier-A (reads out_h[0:HA)) overlaps agg3-B (writes out_h[HA:))
    cudaStreamWaitEvent(S, E[6], 0);
    k_gemm_cls<40><<<HA / 64, 160, SM40, S>>>(out_h, Wc, bc, out_logits, HA);
    cudaEventRecord(E[7], S);
    // main: classifier-B
    k_gemm_cls<40><<<(HB + 63) / 64, 160, SM40>>>(out_h + (size_t)HA * 128, Wc, bc,
                                                  out_logits + (size_t)HA * 40, HB);
    // join side stream back into main before capture ends
    cudaStreamWaitEvent(0, E[7], 0);
}